// round 16
// baseline (speedup 1.0000x reference)
#include <cuda_runtime.h>
#include <math.h>

// Problem constants
#define BB   64
#define TT   512
#define HH   512
#define KG   10
#define NC   80
#define UU   64

#define NBLK 128
#define NTHR 512
#define NGRP 4
#define GBLK 32      // blocks per group
#define BPG  16      // batches per group
#define RPB  64      // gate rows per block (16 h-cols x 4 gates)
#define CPB  16      // h columns per block

// padded K dimension of the fused recurrent GEMM:
//  [0,80)   : w  (W_ih cols 3..83)   -- accumulated via direct LDG, smem stays 0
//  [80,83)  : x  (W_ih cols 0..3)
//  [83]     : zero pad
//  [84,596) : h  (W_hh cols 0..512)
//  [596,612): zero pad
#define KP    612
#define NCH4  153     // KP/4 float4 chunks per row
#define HOFF  84
#define HCH0  21      // first float4 chunk of h region
#define GSTR  17      // gbuf row stride (16 batches + pad)
#define WCH   20      // NC/4: 16B chunks of one step's w row

#define SMEM_FLOATS (RPB*KP + BPG*KP + RPB*GSTR)
#define SMEM_BYTES  (SMEM_FLOATS * 4)

typedef unsigned long long u64;

// packed dual-FMA: d.lo += a.lo*b.lo ; d.hi += a.hi*b.hi  (one FFMA2 op)
__device__ __forceinline__ void ffma2(u64 &d, u64 a, u64 b) {
    asm("fma.rn.f32x2 %0, %1, %2, %0;" : "+l"(d) : "l"(a), "l"(b));
}
__device__ __forceinline__ float hsum2(u64 a) {
    unsigned lo, hi;
    asm("mov.b64 {%0,%1}, %2;" : "=r"(lo), "=r"(hi) : "l"(a));
    return __uint_as_float(lo) + __uint_as_float(hi);
}

// release/acquire primitives (no full MEMBAR)
__device__ __forceinline__ unsigned ld_acq(const unsigned* p) {
    unsigned v;
    asm volatile("ld.acquire.gpu.global.u32 %0, [%1];" : "=r"(v) : "l"(p));
    return v;
}
__device__ __forceinline__ void red_rel_add(unsigned* p, unsigned v) {
    asm volatile("red.release.gpu.global.add.u32 [%0], %1;" :: "l"(p), "r"(v));
}

#define NBAR_SYNC(id, cnt)   asm volatile("bar.sync %0, %1;"   :: "r"(id), "r"(cnt) : "memory")
#define NBAR_ARRIVE(id, cnt) asm volatile("bar.arrive %0, %1;" :: "r"(id), "r"(cnt) : "memory")

// ---------------- per-group sync state (each var on its OWN 128B line) ----
struct alignas(128) SyncLine { unsigned v; unsigned pad[31]; };
__device__ SyncLine g_bar_count[NGRP] = {};   // monotonic arrival counter
__device__ SyncLine g_w_cnt[NGRP]     = {};   // monotonic w(t) publication counter
__device__ SyncLine g_exit[NGRP]      = {};   // end-of-kernel exit counter

// Fence-free monotonic group barrier (never reset during a launch).
__device__ __forceinline__ void group_sync_mono(int grp, unsigned need) {
    __syncthreads();
    if (threadIdx.x == 0) {
        red_rel_add(&g_bar_count[grp].v, 1u);
        while (ld_acq(&g_bar_count[grp].v) < need) { }
    }
    __syncthreads();
}

__device__ __forceinline__ float fsig(float x) {
    return __fdividef(1.0f, 1.0f + __expf(-x));
}
__device__ __forceinline__ float ftanh(float x) {
    x = fminf(fmaxf(x, -15.0f), 15.0f);
    float e = __expf(2.0f * x);
    return __fdividef(e - 1.0f, e + 1.0f);
}

// one c-chunk of the 4b x 4j register-tile GEMM (2 FFMA2 per (i,j))
#define GEMM_STEP(c)                                                     \
    {                                                                    \
        ulonglong2 wv0 = w0[c], wv1 = w1[c], wv2 = w2[c], wv3 = w3[c];   \
        ulonglong2 iv0 = i0[c], iv1 = i1[c], iv2 = i2[c], iv3 = i3[c];   \
        ffma2(acc[0][0], iv0.x, wv0.x); ffma2(acc[0][0], iv0.y, wv0.y);  \
        ffma2(acc[0][1], iv0.x, wv1.x); ffma2(acc[0][1], iv0.y, wv1.y);  \
        ffma2(acc[0][2], iv0.x, wv2.x); ffma2(acc[0][2], iv0.y, wv2.y);  \
        ffma2(acc[0][3], iv0.x, wv3.x); ffma2(acc[0][3], iv0.y, wv3.y);  \
        ffma2(acc[1][0], iv1.x, wv0.x); ffma2(acc[1][0], iv1.y, wv0.y);  \
        ffma2(acc[1][1], iv1.x, wv1.x); ffma2(acc[1][1], iv1.y, wv1.y);  \
        ffma2(acc[1][2], iv1.x, wv2.x); ffma2(acc[1][2], iv1.y, wv2.y);  \
        ffma2(acc[1][3], iv1.x, wv3.x); ffma2(acc[1][3], iv1.y, wv3.y);  \
        ffma2(acc[2][0], iv2.x, wv0.x); ffma2(acc[2][0], iv2.y, wv0.y);  \
        ffma2(acc[2][1], iv2.x, wv1.x); ffma2(acc[2][1], iv2.y, wv1.y);  \
        ffma2(acc[2][2], iv2.x, wv2.x); ffma2(acc[2][2], iv2.y, wv2.y);  \
        ffma2(acc[2][3], iv2.x, wv3.x); ffma2(acc[2][3], iv2.y, wv3.y);  \
        ffma2(acc[3][0], iv3.x, wv0.x); ffma2(acc[3][0], iv3.y, wv0.y);  \
        ffma2(acc[3][1], iv3.x, wv1.x); ffma2(acc[3][1], iv3.y, wv1.y);  \
        ffma2(acc[3][2], iv3.x, wv2.x); ffma2(acc[3][2], iv3.y, wv2.y);  \
        ffma2(acc[3][3], iv3.x, wv3.x); ffma2(acc[3][3], iv3.y, wv3.y);  \
    }

// ---------------- persistent kernel ----------------
__global__ __launch_bounds__(NTHR, 1)
void lstm_attn_kernel(const float* __restrict__ strokes,   // [B,T,3]
                      const int*   __restrict__ sents,     // [B,U]
                      const float* __restrict__ smask,     // [B,U]
                      const float* __restrict__ W_ih,      // [2048,83]
                      const float* __restrict__ W_hh,      // [2048,512]
                      const float* __restrict__ b_ih,      // [2048]
                      const float* __restrict__ b_hh,      // [2048]
                      const float* __restrict__ W_win,     // [30,512]
                      const float* __restrict__ b_win,     // [30]
                      float* __restrict__ out)
{
    extern __shared__ float sm[];
    float* Wsh  = sm;                 // RPB * KP
    float* inp  = Wsh + RPB * KP;     // BPG * KP  (chunks [0,20) stay zero)
    float* gbuf = inp + BPG * KP;     // RPB * GSTR (gates; window blocks reuse as own-h buffer)

    __shared__ float bias_sh[RPB];
    __shared__ float psh[32];
    __shared__ float phi_sh[UU];
    __shared__ int   ssh[UU];
    __shared__ float msh[UU];

    const int tid  = threadIdx.x;
    const int blk  = blockIdx.x;
    const int grp  = blk >> 5;
    const int blkl = blk & 31;
    const int hc0  = blkl * CPB;
    const int gb0  = grp * BPG;
    const bool is_win = (blkl < BPG);

    float* hs_out = out;                               // [B,T,H]
    float* ws_out = out + (size_t)BB * TT * HH;        // [B,T,NC]

    // ---- load this block's 64-row weight slice into smem (once) ----
    for (int e = tid; e < RPB * KP; e += NTHR) {
        int j = e / KP;
        int k = e - j * KP;
        int row = (j >> 4) * HH + hc0 + (j & 15);
        float v = 0.0f;
        if (k < 80)                      v = W_ih[row * 83 + 3 + k];
        else if (k < 83)                 v = W_ih[row * 83 + (k - 80)];
        else if (k >= HOFF && k < HOFF + HH) v = W_hh[row * HH + (k - HOFF)];
        Wsh[e] = v;
    }
    if (tid < RPB) {
        int row = (tid >> 4) * HH + hc0 + (tid & 15);
        bias_sh[tid] = b_ih[row] + b_hh[row];
    }
    if (is_win && tid < UU) {
        ssh[tid] = sents[(gb0 + blkl) * UU + tid];
        msh[tid] = smask[(gb0 + blkl) * UU + tid];
    }

    // ---- zero-init input tile, stage x(0) ----
    {
        float4* inp4 = (float4*)inp;
        float4 z = make_float4(0.f, 0.f, 0.f, 0.f);
        for (int idx = tid; idx < BPG * NCH4; idx += NTHR)
            inp4[idx] = z;
        __syncthreads();
        if (tid < BPG) {
            const float* xp = strokes + (size_t)(gb0 + tid) * TT * 3;
            inp4[tid * NCH4 + 20] = make_float4(xp[0], xp[1], xp[2], 0.f);
        }
    }

    // GEMM mapping: 4b x 4j per-thread tile, k split across 8 threads.
    // Batch rows strided by 4 (bcl + {0,4,8,12}).
    const int ks      = tid & 7;
    const int cluster = tid >> 3;
    const int bcl = cluster & 3;
    const int j0  = (cluster >> 2) * 4;
    // cell-update mapping (threads 0..255)
    const int lb  = tid >> 4;
    const int col = tid & 15;
    float c_state = 0.0f;
    float kappa_reg = 0.0f;     // warp0 lanes 0..9 of window blocks

    const ulonglong2* w0 = (const ulonglong2*)(Wsh + (j0 + 0) * KP);
    const ulonglong2* w1 = (const ulonglong2*)(Wsh + (j0 + 1) * KP);
    const ulonglong2* w2 = (const ulonglong2*)(Wsh + (j0 + 2) * KP);
    const ulonglong2* w3 = (const ulonglong2*)(Wsh + (j0 + 3) * KP);
    const ulonglong2* i0 = (const ulonglong2*)(inp + (bcl + 0)  * KP);
    const ulonglong2* i1 = (const ulonglong2*)(inp + (bcl + 4)  * KP);
    const ulonglong2* i2 = (const ulonglong2*)(inp + (bcl + 8)  * KP);
    const ulonglong2* i3 = (const ulonglong2*)(inp + (bcl + 12) * KP);

    // per-thread global base pointers for the direct-LDG w accumulation
    const ulonglong2* wg0 = (const ulonglong2*)(ws_out + (size_t)(gb0 + bcl + 0)  * TT * NC);
    const ulonglong2* wg1 = (const ulonglong2*)(ws_out + (size_t)(gb0 + bcl + 4)  * TT * NC);
    const ulonglong2* wg2 = (const ulonglong2*)(ws_out + (size_t)(gb0 + bcl + 8)  * TT * NC);
    const ulonglong2* wg3 = (const ulonglong2*)(ws_out + (size_t)(gb0 + bcl + 12) * TT * NC);

    u64 acc[4][4];
    #pragma unroll
    for (int i = 0; i < 4; ++i)
        #pragma unroll
        for (int j = 0; j < 4; ++j) acc[i][j] = 0ull;

    __syncthreads();

    // ---- pre-loop partial GEMM: x(0) contribution (h(-1)=0, w(-1)=0) ----
    #pragma unroll 2
    for (int c = 20 + ks; c < NCH4; c += 8)
        GEMM_STEP(c);

    for (int t = 0; t < TT; ++t) {
        // ======== TOP: accs already hold w+x+h contributions ========
        __syncthreads();   // bottom-phase gbuf reads complete before reduce writes

        // ---- reduce over the 8 k-split lanes -> gbuf ----
        #pragma unroll
        for (int i = 0; i < 4; ++i)
            #pragma unroll
            for (int j = 0; j < 4; ++j) {
                float a = hsum2(acc[i][j]);
                a += __shfl_xor_sync(0xffffffffu, a, 1);
                a += __shfl_xor_sync(0xffffffffu, a, 2);
                a += __shfl_xor_sync(0xffffffffu, a, 4);
                if (ks == 0) gbuf[(j0 + j) * GSTR + (bcl + 4 * i)] = a;
                acc[i][j] = 0ull;
            }
        __syncthreads();

        // ======== LSTM cell update (threads 0..255) + x(t+1) stage (threads 256..271) ========
        if (tid < 256) {
            float gi = gbuf[(0 * 16 + col) * GSTR + lb] + bias_sh[col];
            float gf = gbuf[(1 * 16 + col) * GSTR + lb] + bias_sh[16 + col];
            float gg = gbuf[(2 * 16 + col) * GSTR + lb] + bias_sh[32 + col];
            float go = gbuf[(3 * 16 + col) * GSTR + lb] + bias_sh[48 + col];
            c_state = fsig(gf) * c_state + fsig(gi) * ftanh(gg);
            float h = fsig(go) * ftanh(c_state);
            hs_out[((size_t)(gb0 + lb) * TT + t) * HH + hc0 + col] = h;
        } else if (tid < 256 + BPG) {
            int b = tid - 256;
            int tn = (t + 1 < TT) ? (t + 1) : (TT - 1);
            const float* xp = strokes + ((size_t)(gb0 + b) * TT + tn) * 3;
            ((float4*)inp)[b * NCH4 + 20] = make_float4(xp[0], xp[1], xp[2], 0.f);
        }

        group_sync_mono(grp, 32u * (unsigned)(t + 1));   // h(t) fully visible

        // ======== BOTTOM: role-specialized window / h-staging ========
        if (is_win) {
            if (tid < 128) {
                // warps 0-3: fetch OWN batch's h(t) into gbuf, compute p, publish w
                ((float4*)gbuf)[tid] =
                    __ldcg((const float4*)(hs_out + ((size_t)(gb0 + blkl) * TT + t) * HH + tid * 4));
                NBAR_SYNC(1, 128);

                {   // p[30] = h @ W_win.T + b_win   (4 threads per output)
                    int j = tid >> 2;          // 0..31 (30 real)
                    int seg = tid & 3;
                    float part = 0.0f;
                    if (j < 30) {
                        const float4* wr = (const float4*)(W_win + j * HH + seg * 128);
                        const float4* hr = (const float4*)gbuf + seg * 32;
                        #pragma unroll
                        for (int m = 0; m < 32; ++m) {
                            float4 wv = wr[m];
                            float4 hv = hr[m];
                            part = fmaf(hv.x, wv.x, part);
                            part = fmaf(hv.y, wv.y, part);
                            part = fmaf(hv.z, wv.z, part);
                            part = fmaf(hv.w, wv.w, part);
                        }
                    }
                    part += __shfl_down_sync(0xffffffffu, part, 2, 4);
                    part += __shfl_down_sync(0xffffffffu, part, 1, 4);
                    if (seg == 0 && j < 30) psh[j] = part + b_win[j];
                }
                NBAR_SYNC(1, 128);

                if (tid < 32) {   // warp 0: window math + early publish
                    const int lane = tid;
                    float al = 0.f, be = 0.f;
                    if (lane < KG) {
                        al = __expf(psh[lane]);
                        be = __expf(psh[10 + lane]);
                        kappa_reg += __expf(psh[20 + lane]);
                    }
                    float u0 = (float)lane, u1 = (float)(lane + 32);
                    float ph0 = 0.f, ph1 = 0.f;
                    #pragma unroll
                    for (int k = 0; k < KG; ++k) {
                        float av = __shfl_sync(0xffffffffu, al, k);
                        float bv = __shfl_sync(0xffffffffu, be, k);
                        float kv = __shfl_sync(0xffffffffu, kappa_reg, k);
                        float d0 = kv - u0;
                        float d1 = kv - u1;
                        ph0 = fmaf(av, __expf(-bv * d0 * d0), ph0);
                        ph1 = fmaf(av, __expf(-bv * d1 * d1), ph1);
                    }
                    phi_sh[lane]      = ph0 * msh[lane];
                    phi_sh[lane + 32] = ph1 * msh[lane + 32];
                    __syncwarp();

                    float wa0 = 0.f, wa1 = 0.f, wa2 = 0.f;
                    int n0 = lane, n1 = lane + 32, n2 = lane + 64;
                    #pragma unroll 8
                    for (int u = 0; u < UU; ++u) {
                        int   s  = ssh[u];
                        float pv = phi_sh[u];
                        wa0 += (s == n0) ? pv : 0.f;
                        wa1 += (s == n1) ? pv : 0.f;
                        wa2 += (s == n2) ? pv : 0.f;
                    }
                    float* wout = ws_out + ((size_t)(gb0 + blkl) * TT + t) * NC;
                    wout[n0] = wa0;
                    wout[n1] = wa1;
                    if (lane < 16) wout[n2] = wa2;
                    __syncwarp();
                    if (lane == 0) red_rel_add(&g_w_cnt[grp].v, 1u);  // early publish
                }
                NBAR_SYNC(3, 512);          // wait for h-region staging (warps 4-15)
            } else {
                // warps 4-15: stage the full h(t) region while window runs
                float4* inp4 = (float4*)inp;
                for (int idx = tid - 128; idx < BPG * 128; idx += 384) {
                    int b = idx >> 7;
                    int c = idx & 127;
                    inp4[b * NCH4 + HCH0 + c] =
                        __ldcg((const float4*)(hs_out + ((size_t)(gb0 + b) * TT + t) * HH + c * 4));
                }
                NBAR_SYNC(2, 384);          // staging complete among stagers
                NBAR_ARRIVE(3, 512);        // release warps 0-3 into pGEMM
            }
        } else {
            // non-window block: uniform staging
            float4* inp4 = (float4*)inp;
            #pragma unroll 4
            for (int idx = tid; idx < BPG * 128; idx += NTHR) {
                int b = idx >> 7;
                int c = idx & 127;
                inp4[b * NCH4 + HCH0 + c] =
                    __ldcg((const float4*)(hs_out + ((size_t)(gb0 + b) * TT + t) * HH + c * 4));
            }
            __syncthreads();
        }

        // ======== partial GEMM for step t+1: chunks [20,153) (h + x) ========
        #pragma unroll 2
        for (int c = 20 + ks; c < NCH4; c += 8)
            GEMM_STEP(c);

        // ======== w-part accumulation via direct LDG (pGEMM shadow) ========
        // w(t) was published ~6K cycles ago; the spin passes immediately.
        if (t + 1 < TT) {
            if ((tid & 31) == 0) {
                unsigned need = 16u * (unsigned)(t + 1);
                while (ld_acq(&g_w_cnt[grp].v) < need) { }
            }
            __syncwarp();
            const size_t roff = (size_t)t * WCH;   // NC/4 = 20 chunks per step row
            #pragma unroll 1
            for (int c = ks; c < 20; c += 8) {
                ulonglong2 iv0 = __ldcg(wg0 + roff + c);
                ulonglong2 iv1 = __ldcg(wg1 + roff + c);
                ulonglong2 iv2 = __ldcg(wg2 + roff + c);
                ulonglong2 iv3 = __ldcg(wg3 + roff + c);
                ulonglong2 wv0 = w0[c], wv1 = w1[c], wv2 = w2[c], wv3 = w3[c];
                ffma2(acc[0][0], iv0.x, wv0.x); ffma2(acc[0][0], iv0.y, wv0.y);
                ffma2(acc[0][1], iv0.x, wv1.x); ffma2(acc[0][1], iv0.y, wv1.y);
                ffma2(acc[0][2], iv0.x, wv2.x); ffma2(acc[0][2], iv0.y, wv2.y);
                ffma2(acc[0][3], iv0.x, wv3.x); ffma2(acc[0][3], iv0.y, wv3.y);
                ffma2(acc[1][0], iv1.x, wv0.x); ffma2(acc[1][0], iv1.y, wv0.y);
                ffma2(acc[1][1], iv1.x, wv1.x); ffma2(acc[1][1], iv1.y, wv1.y);
                ffma2(acc[1][2], iv1.x, wv2.x); ffma2(acc[1][2], iv1.y, wv2.y);
                ffma2(acc[1][3], iv1.x, wv3.x); ffma2(acc[1][3], iv1.y, wv3.y);
                ffma2(acc[2][0], iv2.x, wv0.x); ffma2(acc[2][0], iv2.y, wv0.y);
                ffma2(acc[2][1], iv2.x, wv1.x); ffma2(acc[2][1], iv2.y, wv1.y);
                ffma2(acc[2][2], iv2.x, wv2.x); ffma2(acc[2][2], iv2.y, wv2.y);
                ffma2(acc[2][3], iv2.x, wv3.x); ffma2(acc[2][3], iv2.y, wv3.y);
                ffma2(acc[3][0], iv3.x, wv0.x); ffma2(acc[3][0], iv3.y, wv0.y);
                ffma2(acc[3][1], iv3.x, wv1.x); ffma2(acc[3][1], iv3.y, wv1.y);
                ffma2(acc[3][2], iv3.x, wv2.x); ffma2(acc[3][2], iv3.y, wv2.y);
                ffma2(acc[3][3], iv3.x, wv3.x); ffma2(acc[3][3], iv3.y, wv3.y);
            }
        }
    }

    // ======== race-free termination + counter reset ========
    // Each block arrives on the exit counter and leaves; ONLY block (grp,0)
    // polls and resets. No block reads any counter after its final arrival,
    // so the reset cannot race with a poll. Kernel completion orders the
    // plain-store resets before the next graph replay.
    __syncthreads();
    if (tid == 0) {
        red_rel_add(&g_exit[grp].v, 1u);
        if (blkl == 0) {
            while (ld_acq(&g_exit[grp].v) < (unsigned)GBLK) { }
            g_bar_count[grp].v = 0;
            g_w_cnt[grp].v     = 0;
            g_exit[grp].v      = 0;
        }
    }
}

// ---------------- launch ----------------
extern "C" void kernel_launch(void* const* d_in, const int* in_sizes, int n_in,
                              void* d_out, int out_size) {
    const float* strokes = (const float*)d_in[0];
    const int*   sents   = (const int*)  d_in[1];
    const float* smaskp  = (const float*)d_in[2];
    const float* W_ih    = (const float*)d_in[3];
    const float* W_hh    = (const float*)d_in[4];
    const float* b_ih    = (const float*)d_in[5];
    const float* b_hh    = (const float*)d_in[6];
    const float* W_win   = (const float*)d_in[7];
    const float* b_win   = (const float*)d_in[8];
    float* out = (float*)d_out;

    cudaFuncSetAttribute(lstm_attn_kernel,
                         cudaFuncAttributeMaxDynamicSharedMemorySize, SMEM_BYTES);

    lstm_attn_kernel<<<NBLK, NTHR, SMEM_BYTES>>>(
        strokes, sents, smaskp, W_ih, W_hh, b_ih, b_hh, W_win, b_win, out);
}

// round 17
// speedup vs baseline: 1.6410x; 1.6410x over previous
#include <cuda_runtime.h>
#include <math.h>

// Problem constants
#define BB   64
#define TT   512
#define HH   512
#define KG   10
#define NC   80
#define UU   64

#define NBLK 128
#define NTHR 512
#define NGRP 4
#define GBLK 32      // blocks per group
#define BPG  16      // batches per group
#define RPB  64      // gate rows per block (16 h-cols x 4 gates)
#define CPB  16      // h columns per block

// padded K dimension of the fused recurrent GEMM:
//  [0,80)   : w  (W_ih cols 3..83)
//  [80,83)  : x  (W_ih cols 0..3)
//  [83]     : zero pad
//  [84,596) : h  (W_hh cols 0..512)
//  [596,612): zero pad
#define KP    612
#define NCH4  153     // KP/4 float4 chunks per row
#define HOFF  84
#define HCH0  21      // first float4 chunk of h region
#define GSTR  17      // gbuf row stride (16 batches + pad)

#define SMEM_FLOATS (RPB*KP + BPG*KP + RPB*GSTR)
#define SMEM_BYTES  (SMEM_FLOATS * 4)

typedef unsigned long long u64;

// packed dual-FMA: d.lo += a.lo*b.lo ; d.hi += a.hi*b.hi  (one FFMA2 op)
__device__ __forceinline__ void ffma2(u64 &d, u64 a, u64 b) {
    asm("fma.rn.f32x2 %0, %1, %2, %0;" : "+l"(d) : "l"(a), "l"(b));
}
__device__ __forceinline__ float hsum2(u64 a) {
    unsigned lo, hi;
    asm("mov.b64 {%0,%1}, %2;" : "=r"(lo), "=r"(hi) : "l"(a));
    return __uint_as_float(lo) + __uint_as_float(hi);
}

// release/acquire primitives (no full MEMBAR)
__device__ __forceinline__ unsigned ld_acq(const unsigned* p) {
    unsigned v;
    asm volatile("ld.acquire.gpu.global.u32 %0, [%1];" : "=r"(v) : "l"(p));
    return v;
}
__device__ __forceinline__ void red_rel_add(unsigned* p, unsigned v) {
    asm volatile("red.release.gpu.global.add.u32 [%0], %1;" :: "l"(p), "r"(v));
}

#define NBAR_SYNC(id, cnt)   asm volatile("bar.sync %0, %1;"   :: "r"(id), "r"(cnt) : "memory")
#define NBAR_ARRIVE(id, cnt) asm volatile("bar.arrive %0, %1;" :: "r"(id), "r"(cnt) : "memory")

// ---------------- per-group sync state (each var on its OWN 128B line) ----
struct alignas(128) SyncLine { unsigned v; unsigned pad[31]; };
__device__ SyncLine g_bar_count[NGRP] = {};   // monotonic arrival counter
__device__ SyncLine g_w_cnt[NGRP]     = {};   // monotonic w(t) publication counter
__device__ SyncLine g_exit[NGRP]      = {};   // end-of-kernel exit counter

// Fence-free monotonic group barrier (never reset during a launch).
__device__ __forceinline__ void group_sync_mono(int grp, unsigned need) {
    __syncthreads();
    if (threadIdx.x == 0) {
        red_rel_add(&g_bar_count[grp].v, 1u);
        while (ld_acq(&g_bar_count[grp].v) < need) { }
    }
    __syncthreads();
}

__device__ __forceinline__ float fsig(float x) {
    return __fdividef(1.0f, 1.0f + __expf(-x));
}
__device__ __forceinline__ float ftanh(float x) {
    x = fminf(fmaxf(x, -15.0f), 15.0f);
    float e = __expf(2.0f * x);
    return __fdividef(e - 1.0f, e + 1.0f);
}

// one c-chunk of the 4b x 4j register-tile GEMM (2 FFMA2 per (i,j))
#define GEMM_STEP(c)                                                     \
    {                                                                    \
        ulonglong2 wv0 = w0[c], wv1 = w1[c], wv2 = w2[c], wv3 = w3[c];   \
        ulonglong2 iv0 = i0[c], iv1 = i1[c], iv2 = i2[c], iv3 = i3[c];   \
        ffma2(acc[0][0], iv0.x, wv0.x); ffma2(acc[0][0], iv0.y, wv0.y);  \
        ffma2(acc[0][1], iv0.x, wv1.x); ffma2(acc[0][1], iv0.y, wv1.y);  \
        ffma2(acc[0][2], iv0.x, wv2.x); ffma2(acc[0][2], iv0.y, wv2.y);  \
        ffma2(acc[0][3], iv0.x, wv3.x); ffma2(acc[0][3], iv0.y, wv3.y);  \
        ffma2(acc[1][0], iv1.x, wv0.x); ffma2(acc[1][0], iv1.y, wv0.y);  \
        ffma2(acc[1][1], iv1.x, wv1.x); ffma2(acc[1][1], iv1.y, wv1.y);  \
        ffma2(acc[1][2], iv1.x, wv2.x); ffma2(acc[1][2], iv1.y, wv2.y);  \
        ffma2(acc[1][3], iv1.x, wv3.x); ffma2(acc[1][3], iv1.y, wv3.y);  \
        ffma2(acc[2][0], iv2.x, wv0.x); ffma2(acc[2][0], iv2.y, wv0.y);  \
        ffma2(acc[2][1], iv2.x, wv1.x); ffma2(acc[2][1], iv2.y, wv1.y);  \
        ffma2(acc[2][2], iv2.x, wv2.x); ffma2(acc[2][2], iv2.y, wv2.y);  \
        ffma2(acc[2][3], iv2.x, wv3.x); ffma2(acc[2][3], iv2.y, wv3.y);  \
        ffma2(acc[3][0], iv3.x, wv0.x); ffma2(acc[3][0], iv3.y, wv0.y);  \
        ffma2(acc[3][1], iv3.x, wv1.x); ffma2(acc[3][1], iv3.y, wv1.y);  \
        ffma2(acc[3][2], iv3.x, wv2.x); ffma2(acc[3][2], iv3.y, wv2.y);  \
        ffma2(acc[3][3], iv3.x, wv3.x); ffma2(acc[3][3], iv3.y, wv3.y);  \
    }

// ---------------- persistent kernel ----------------
__global__ __launch_bounds__(NTHR, 1)
void lstm_attn_kernel(const float* __restrict__ strokes,   // [B,T,3]
                      const int*   __restrict__ sents,     // [B,U]
                      const float* __restrict__ smask,     // [B,U]
                      const float* __restrict__ W_ih,      // [2048,83]
                      const float* __restrict__ W_hh,      // [2048,512]
                      const float* __restrict__ b_ih,      // [2048]
                      const float* __restrict__ b_hh,      // [2048]
                      const float* __restrict__ W_win,     // [30,512]
                      const float* __restrict__ b_win,     // [30]
                      float* __restrict__ out)
{
    extern __shared__ float sm[];
    float* Wsh  = sm;                 // RPB * KP
    float* inp  = Wsh + RPB * KP;     // BPG * KP
    float* gbuf = inp + BPG * KP;     // RPB * GSTR (gates; window blocks reuse as own-h buffer)

    __shared__ float bias_sh[RPB];
    __shared__ float psh[32];
    __shared__ float phi_sh[UU];
    __shared__ int   ssh[UU];
    __shared__ float msh[UU];

    const int tid  = threadIdx.x;
    const int blk  = blockIdx.x;
    const int grp  = blk >> 5;
    const int blkl = blk & 31;
    const int hc0  = blkl * CPB;
    const int gb0  = grp * BPG;
    const bool is_win = (blkl < BPG);

    float* hs_out = out;                               // [B,T,H]
    float* ws_out = out + (size_t)BB * TT * HH;        // [B,T,NC]

    // ---- load this block's 64-row weight slice into smem (once) ----
    for (int e = tid; e < RPB * KP; e += NTHR) {
        int j = e / KP;
        int k = e - j * KP;
        int row = (j >> 4) * HH + hc0 + (j & 15);
        float v = 0.0f;
        if (k < 80)                      v = W_ih[row * 83 + 3 + k];
        else if (k < 83)                 v = W_ih[row * 83 + (k - 80)];
        else if (k >= HOFF && k < HOFF + HH) v = W_hh[row * HH + (k - HOFF)];
        Wsh[e] = v;
    }
    if (tid < RPB) {
        int row = (tid >> 4) * HH + hc0 + (tid & 15);
        bias_sh[tid] = b_ih[row] + b_hh[row];
    }
    if (is_win && tid < UU) {
        ssh[tid] = sents[(gb0 + blkl) * UU + tid];
        msh[tid] = smask[(gb0 + blkl) * UU + tid];
    }

    // ---- zero-init input tile, stage x(0) ----
    {
        float4* inp4 = (float4*)inp;
        float4 z = make_float4(0.f, 0.f, 0.f, 0.f);
        for (int idx = tid; idx < BPG * NCH4; idx += NTHR)
            inp4[idx] = z;
        __syncthreads();
        if (tid < BPG) {
            const float* xp = strokes + (size_t)(gb0 + tid) * TT * 3;
            inp4[tid * NCH4 + 20] = make_float4(xp[0], xp[1], xp[2], 0.f);
        }
    }

    // GEMM mapping: 4b x 4j per-thread tile, k split across 8 threads.
    // Batch rows strided by 4 (bcl + {0,4,8,12}).
    const int ks      = tid & 7;
    const int cluster = tid >> 3;
    const int bcl = cluster & 3;
    const int j0  = (cluster >> 2) * 4;
    // cell-update mapping (threads 0..255)
    const int lb  = tid >> 4;
    const int col = tid & 15;
    // w-prefetch mapping (threads 0..319: one float4 chunk each)
    const int b_pre = tid / 20;
    const int c_pre = tid - b_pre * 20;
    float c_state = 0.0f;
    float kappa_reg = 0.0f;     // warp0 lanes 0..9 of window blocks

    const ulonglong2* w0 = (const ulonglong2*)(Wsh + (j0 + 0) * KP);
    const ulonglong2* w1 = (const ulonglong2*)(Wsh + (j0 + 1) * KP);
    const ulonglong2* w2 = (const ulonglong2*)(Wsh + (j0 + 2) * KP);
    const ulonglong2* w3 = (const ulonglong2*)(Wsh + (j0 + 3) * KP);
    const ulonglong2* i0 = (const ulonglong2*)(inp + (bcl + 0)  * KP);
    const ulonglong2* i1 = (const ulonglong2*)(inp + (bcl + 4)  * KP);
    const ulonglong2* i2 = (const ulonglong2*)(inp + (bcl + 8)  * KP);
    const ulonglong2* i3 = (const ulonglong2*)(inp + (bcl + 12) * KP);

    u64 acc[4][4];
    #pragma unroll
    for (int i = 0; i < 4; ++i)
        #pragma unroll
        for (int j = 0; j < 4; ++j) acc[i][j] = 0ull;

    __syncthreads();

    // ---- pre-loop partial GEMM: x(0) contribution (h(-1)=0; w chunks are zero) ----
    #pragma unroll 2
    for (int c = 20 + ks; c < NCH4; c += 8)
        GEMM_STEP(c);

    for (int t = 0; t < TT; ++t) {
        // ======== TOP: w(t-1) already staged into inp at bottom of t-1 ========
        __syncthreads();   // w-chunk stores (and bottom-phase smem writes) visible

        // ======== w-part GEMM: chunks [0,20) ========
        {
            #pragma unroll 1
            for (int c = ks; c < 20; c += 8)
                GEMM_STEP(c);

            #pragma unroll
            for (int i = 0; i < 4; ++i)
                #pragma unroll
                for (int j = 0; j < 4; ++j) {
                    float a = hsum2(acc[i][j]);
                    a += __shfl_xor_sync(0xffffffffu, a, 1);
                    a += __shfl_xor_sync(0xffffffffu, a, 2);
                    a += __shfl_xor_sync(0xffffffffu, a, 4);
                    if (ks == 0) gbuf[(j0 + j) * GSTR + (bcl + 4 * i)] = a;
                    acc[i][j] = 0ull;
                }
        }
        __syncthreads();

        // ======== LSTM cell update (threads 0..255) + x(t+1) stage (threads 256..271) ========
        if (tid < 256) {
            float gi = gbuf[(0 * 16 + col) * GSTR + lb] + bias_sh[col];
            float gf = gbuf[(1 * 16 + col) * GSTR + lb] + bias_sh[16 + col];
            float gg = gbuf[(2 * 16 + col) * GSTR + lb] + bias_sh[32 + col];
            float go = gbuf[(3 * 16 + col) * GSTR + lb] + bias_sh[48 + col];
            c_state = fsig(gf) * c_state + fsig(gi) * ftanh(gg);
            float h = fsig(go) * ftanh(c_state);
            hs_out[((size_t)(gb0 + lb) * TT + t) * HH + hc0 + col] = h;
        } else if (tid < 256 + BPG) {
            int b = tid - 256;
            int tn = (t + 1 < TT) ? (t + 1) : (TT - 1);
            const float* xp = strokes + ((size_t)(gb0 + b) * TT + tn) * 3;
            ((float4*)inp)[b * NCH4 + 20] = make_float4(xp[0], xp[1], xp[2], 0.f);
        }

        group_sync_mono(grp, 32u * (unsigned)(t + 1));   // h(t) fully visible

        // ======== BOTTOM: role-specialized window / h-staging ========
        if (is_win) {
            if (tid < 128) {
                // warps 0-3: fetch OWN batch's h(t) into gbuf, compute p, publish w
                ((float4*)gbuf)[tid] =
                    __ldcg((const float4*)(hs_out + ((size_t)(gb0 + blkl) * TT + t) * HH + tid * 4));
                NBAR_SYNC(1, 128);

                {   // p[30] = h @ W_win.T + b_win   (4 threads per output)
                    int j = tid >> 2;          // 0..31 (30 real)
                    int seg = tid & 3;
                    float part = 0.0f;
                    if (j < 30) {
                        const float4* wr = (const float4*)(W_win + j * HH + seg * 128);
                        const float4* hr = (const float4*)gbuf + seg * 32;
                        #pragma unroll
                        for (int m = 0; m < 32; ++m) {
                            float4 wv = wr[m];
                            float4 hv = hr[m];
                            part = fmaf(hv.x, wv.x, part);
                            part = fmaf(hv.y, wv.y, part);
                            part = fmaf(hv.z, wv.z, part);
                            part = fmaf(hv.w, wv.w, part);
                        }
                    }
                    part += __shfl_down_sync(0xffffffffu, part, 2, 4);
                    part += __shfl_down_sync(0xffffffffu, part, 1, 4);
                    if (seg == 0 && j < 30) psh[j] = part + b_win[j];
                }
                NBAR_SYNC(1, 128);

                if (tid < 32) {   // warp 0: window math + early publish
                    const int lane = tid;
                    float al = 0.f, be = 0.f;
                    if (lane < KG) {
                        al = __expf(psh[lane]);
                        be = __expf(psh[10 + lane]);
                        kappa_reg += __expf(psh[20 + lane]);
                    }
                    float u0 = (float)lane, u1 = (float)(lane + 32);
                    float ph0 = 0.f, ph1 = 0.f;
                    #pragma unroll
                    for (int k = 0; k < KG; ++k) {
                        float av = __shfl_sync(0xffffffffu, al, k);
                        float bv = __shfl_sync(0xffffffffu, be, k);
                        float kv = __shfl_sync(0xffffffffu, kappa_reg, k);
                        float d0 = kv - u0;
                        float d1 = kv - u1;
                        ph0 = fmaf(av, __expf(-bv * d0 * d0), ph0);
                        ph1 = fmaf(av, __expf(-bv * d1 * d1), ph1);
                    }
                    phi_sh[lane]      = ph0 * msh[lane];
                    phi_sh[lane + 32] = ph1 * msh[lane + 32];
                    __syncwarp();

                    float wa0 = 0.f, wa1 = 0.f, wa2 = 0.f;
                    int n0 = lane, n1 = lane + 32, n2 = lane + 64;
                    #pragma unroll 8
                    for (int u = 0; u < UU; ++u) {
                        int   s  = ssh[u];
                        float pv = phi_sh[u];
                        wa0 += (s == n0) ? pv : 0.f;
                        wa1 += (s == n1) ? pv : 0.f;
                        wa2 += (s == n2) ? pv : 0.f;
                    }
                    float* wout = ws_out + ((size_t)(gb0 + blkl) * TT + t) * NC;
                    wout[n0] = wa0;
                    wout[n1] = wa1;
                    if (lane < 16) wout[n2] = wa2;
                    __syncwarp();
                    if (lane == 0) red_rel_add(&g_w_cnt[grp].v, 1u);  // early publish
                }
                NBAR_SYNC(3, 512);          // wait for h-region staging (warps 4-15)
            } else {
                // warps 4-15: stage the full h(t) region while window runs
                float4* inp4 = (float4*)inp;
                for (int idx = tid - 128; idx < BPG * 128; idx += 384) {
                    int b = idx >> 7;
                    int c = idx & 127;
                    inp4[b * NCH4 + HCH0 + c] =
                        __ldcg((const float4*)(hs_out + ((size_t)(gb0 + b) * TT + t) * HH + c * 4));
                }
                NBAR_SYNC(2, 384);          // staging complete among stagers
                NBAR_ARRIVE(3, 512);        // release warps 0-3 into pGEMM
            }
        } else {
            // non-window block: uniform staging
            float4* inp4 = (float4*)inp;
            #pragma unroll 4
            for (int idx = tid; idx < BPG * 128; idx += NTHR) {
                int b = idx >> 7;
                int c = idx & 127;
                inp4[b * NCH4 + HCH0 + c] =
                    __ldcg((const float4*)(hs_out + ((size_t)(gb0 + b) * TT + t) * HH + c * 4));
            }
            __syncthreads();
        }

        // ======== partial GEMM for step t+1: chunks [20,153) (h + x) ========
        #pragma unroll 2
        for (int c = 20 + ks; c < NCH4; c += 8)
            GEMM_STEP(c);

        // ======== prefetch w(t) into inp w-chunks (warps 0-9, pGEMM shadow) ========
        // pGEMM never reads chunks [0,20); last reader was this step's wGEMM,
        // separated by the pre-cell __syncthreads. Next reader is behind the
        // top __syncthreads of step t+1.
        if (t + 1 < TT && tid < 320) {
            if ((tid & 31) == 0) {
                unsigned need = 16u * (unsigned)(t + 1);
                while (ld_acq(&g_w_cnt[grp].v) < need) { }
            }
            __syncwarp();
            ((float4*)inp)[b_pre * NCH4 + c_pre] =
                __ldcg((const float4*)(ws_out + ((size_t)(gb0 + b_pre) * TT + t) * NC + c_pre * 4));
        }
    }

    // ======== race-free termination + counter reset ========
    // Each block arrives once on the exit counter and leaves; ONLY block
    // (grp,0) polls and resets. No block reads any counter after its final
    // arrival, so the reset cannot race with a poll. Kernel completion
    // orders the plain-store resets before the next graph replay.
    __syncthreads();
    if (tid == 0) {
        red_rel_add(&g_exit[grp].v, 1u);
        if (blkl == 0) {
            while (ld_acq(&g_exit[grp].v) < (unsigned)GBLK) { }
            g_bar_count[grp].v = 0;
            g_w_cnt[grp].v     = 0;
            g_exit[grp].v      = 0;
        }
    }
}

// ---------------- launch ----------------
extern "C" void kernel_launch(void* const* d_in, const int* in_sizes, int n_in,
                              void* d_out, int out_size) {
    const float* strokes = (const float*)d_in[0];
    const int*   sents   = (const int*)  d_in[1];
    const float* smaskp  = (const float*)d_in[2];
    const float* W_ih    = (const float*)d_in[3];
    const float* W_hh    = (const float*)d_in[4];
    const float* b_ih    = (const float*)d_in[5];
    const float* b_hh    = (const float*)d_in[6];
    const float* W_win   = (const float*)d_in[7];
    const float* b_win   = (const float*)d_in[8];
    float* out = (float*)d_out;

    cudaFuncSetAttribute(lstm_attn_kernel,
                         cudaFuncAttributeMaxDynamicSharedMemorySize, SMEM_BYTES);

    lstm_attn_kernel<<<NBLK, NTHR, SMEM_BYTES>>>(
        strokes, sents, smaskp, W_ih, W_hh, b_ih, b_hh, W_win, b_win, out);
}